// round 1
// baseline (speedup 1.0000x reference)
#include <cuda_runtime.h>
#include <cstdint>

#define BATCH 64
#define DIM 1024
#define KSPLIT 8
#define KCHUNK 128   // DIM / KSPLIT

// ---- scratch (device globals; no allocations allowed) ----
__device__ float g_part[3][KSPLIT][BATCH * DIM];  // split-K partials: 0=qp, 1=kp, 2=g2
__device__ float g_qp[BATCH * DIM];
__device__ float g_kp[BATCH * DIM];
__device__ float g_g2[BATCH * DIM];
__device__ float g_w1s[DIM];

__device__ __forceinline__ float frcp(float x) {
    float r;
    asm("rcp.approx.f32 %0, %1;" : "=f"(r) : "f"(x));
    return r;
}

// ---------------------------------------------------------------------------
// Split-K GEMM partials: part[sel][sp][b*DIM+o] = sum_{k in split sp} in[b,k]*W[o, off+k]
// sel 0: qp = q @ Wq^T   sel 1: kp = k @ Wk^T   sel 2: g2 = kp @ W2^T (W2 = Wg[:,DIM:])
// Tile: M=64 (all batches) x N=64, K-chunk 128 per block. grid = (16, KSPLIT, ngemm)
// ---------------------------------------------------------------------------
__global__ __launch_bounds__(256) void gemm_part(
    int sel_base,
    const float* __restrict__ q, const float* __restrict__ k,
    const float* __restrict__ Wq, const float* __restrict__ Wk,
    const float* __restrict__ Wg)
{
    int sel = sel_base + blockIdx.z;
    const float* in;
    const float* W;
    int ld, off;
    if (sel == 0)      { in = q;    W = Wq; ld = DIM;     off = 0;   }
    else if (sel == 1) { in = k;    W = Wk; ld = DIM;     off = 0;   }
    else               { in = g_kp; W = Wg; ld = 2 * DIM; off = DIM; }
    float* part = &g_part[sel][blockIdx.y][0];

    const int o0 = blockIdx.x * 64;
    const int k0 = blockIdx.y * KCHUNK;

    __shared__ __align__(16) float As[32][68];  // [k][m], padded row
    __shared__ __align__(16) float Bs[32][68];  // [k][n]

    const int t  = threadIdx.x;
    const int tx = t & 15;   // n / 4
    const int ty = t >> 4;   // m / 4

    float acc[4][4];
#pragma unroll
    for (int i = 0; i < 4; i++)
#pragma unroll
        for (int j = 0; j < 4; j++) acc[i][j] = 0.f;

    for (int kc = 0; kc < KCHUNK; kc += 32) {
#pragma unroll
        for (int it = 0; it < 2; it++) {
            int m  = (t >> 3) + it * 32;  // 0..63
            int kq = t & 7;               // 0..7 (x4 k-values)
            float4 va = *reinterpret_cast<const float4*>(&in[m * DIM + k0 + kc + kq * 4]);
            As[kq * 4 + 0][m] = va.x; As[kq * 4 + 1][m] = va.y;
            As[kq * 4 + 2][m] = va.z; As[kq * 4 + 3][m] = va.w;
            float4 vb = *reinterpret_cast<const float4*>(&W[(size_t)(o0 + m) * ld + off + k0 + kc + kq * 4]);
            Bs[kq * 4 + 0][m] = vb.x; Bs[kq * 4 + 1][m] = vb.y;
            Bs[kq * 4 + 2][m] = vb.z; Bs[kq * 4 + 3][m] = vb.w;
        }
        __syncthreads();
#pragma unroll
        for (int kk = 0; kk < 32; kk++) {
            float4 a  = *reinterpret_cast<const float4*>(&As[kk][ty * 4]);
            float4 bv = *reinterpret_cast<const float4*>(&Bs[kk][tx * 4]);
            acc[0][0] = fmaf(a.x, bv.x, acc[0][0]);
            acc[0][1] = fmaf(a.x, bv.y, acc[0][1]);
            acc[0][2] = fmaf(a.x, bv.z, acc[0][2]);
            acc[0][3] = fmaf(a.x, bv.w, acc[0][3]);
            acc[1][0] = fmaf(a.y, bv.x, acc[1][0]);
            acc[1][1] = fmaf(a.y, bv.y, acc[1][1]);
            acc[1][2] = fmaf(a.y, bv.z, acc[1][2]);
            acc[1][3] = fmaf(a.y, bv.w, acc[1][3]);
            acc[2][0] = fmaf(a.z, bv.x, acc[2][0]);
            acc[2][1] = fmaf(a.z, bv.y, acc[2][1]);
            acc[2][2] = fmaf(a.z, bv.z, acc[2][2]);
            acc[2][3] = fmaf(a.z, bv.w, acc[2][3]);
            acc[3][0] = fmaf(a.w, bv.x, acc[3][0]);
            acc[3][1] = fmaf(a.w, bv.y, acc[3][1]);
            acc[3][2] = fmaf(a.w, bv.z, acc[3][2]);
            acc[3][3] = fmaf(a.w, bv.w, acc[3][3]);
        }
        __syncthreads();
    }

#pragma unroll
    for (int i = 0; i < 4; i++) {
        float4 v = make_float4(acc[i][0], acc[i][1], acc[i][2], acc[i][3]);
        *reinterpret_cast<float4*>(&part[(ty * 4 + i) * DIM + o0 + tx * 4]) = v;
    }
}

// reduce split-K partials + bias.  grid = (BATCH*DIM/256, ngemm)
__global__ __launch_bounds__(256) void reduce_part(
    int sel_base, const float* __restrict__ b0, const float* __restrict__ b1)
{
    int sel = sel_base + blockIdx.y;
    const float* bias = (blockIdx.y == 0) ? b0 : b1;
    float* dst = (sel == 0) ? g_qp : (sel == 1) ? g_kp : g_g2;
    int idx = blockIdx.x * 256 + threadIdx.x;
    float s = bias[idx & (DIM - 1)];
#pragma unroll
    for (int sp = 0; sp < KSPLIT; sp++) s += g_part[sel][sp][idx];
    dst[idx] = s;
}

// w1_row_sum[j] = sum_{c<DIM} Wg[j, c].  One warp per row. grid = 128 x 256
__global__ __launch_bounds__(256) void w1s_kernel(const float* __restrict__ Wg)
{
    int gw   = (blockIdx.x * 256 + threadIdx.x) >> 5;  // 0..1023
    int lane = threadIdx.x & 31;
    const float* row = Wg + (size_t)gw * (2 * DIM);
    float s = 0.f;
#pragma unroll
    for (int i = 0; i < 8; i++) {
        float4 v = *reinterpret_cast<const float4*>(&row[lane * 4 + i * 128]);
        s += v.x + v.y + v.z + v.w;
    }
#pragma unroll
    for (int o = 16; o; o >>= 1) s += __shfl_xor_sync(0xffffffffu, s, o);
    if (lane == 0) g_w1s[gw] = s;
}

// ---------------------------------------------------------------------------
// Fused scores*gate + softmax, single pass over the 256 MB output.
//   x[b,i,j] = qp[b,i]*kp[b,j] * sigma(sigma(qp[b,i]*w1s[j] + g2[b,j]))
//   out[b,i,:] = softmax_j(x)   (max-subtraction provably unneeded: |x| <= ~7)
// inner sigma: 1/(1+exp2(-log2e*arg))  (EX2 + RCP, accurate)
// outer sigma: argument in (0,1) -> degree-7 odd Taylor poly (err <= 2.1e-5)
// Block = 128 thr x 8 elems/thr (j = u*128+tid), 16 rows/block of one batch.
// Per-j coefficients pre-scaled into registers once per block.
// ---------------------------------------------------------------------------
__global__ __launch_bounds__(128) void fused_softmax(float* __restrict__ out)
{
    const int b   = blockIdx.x;
    const int i0  = blockIdx.y * 16;
    const int tid = threadIdx.x;

    __shared__ float qs[16];
    __shared__ float ps[2][4];

    const float L2E = 1.4426950408889634f;
    float a2[8], c2[8], d2[8];
#pragma unroll
    for (int u = 0; u < 8; u++) {
        int j = u * 128 + tid;
        a2[u] = g_kp[b * DIM + j] * L2E;     // exp arg scale folded in
        c2[u] = -L2E * g_w1s[j];             // inner-sigmoid exp2 coeffs
        d2[u] = -L2E * g_g2[b * DIM + j];
    }
    if (tid < 16) qs[tid] = g_qp[b * DIM + i0 + tid];
    __syncthreads();

    const int w = tid >> 5, lane = tid & 31;
    const float C1 = 0.25f, C3 = -1.0f / 48.0f, C5 = 1.0f / 480.0f, C7 = -17.0f / 80640.0f;

    for (int r = 0; r < 16; r++) {
        const float qi = qs[r];
        float e[8];
        float loc = 0.f;
#pragma unroll
        for (int u = 0; u < 8; u++) {
            float E    = exp2f(fmaf(qi, c2[u], d2[u]));   // exp(-gate_pre)
            float s1   = frcp(1.0f + E);                  // inner sigmoid
            float u2   = s1 * s1;                         // outer sigmoid: poly
            float p    = fmaf(u2, C7, C5);
            p          = fmaf(u2, p, C3);
            p          = fmaf(u2, p, C1);
            float gate = fmaf(s1, p, 0.5f);
            e[u] = exp2f(qi * a2[u] * gate);              // exp(scores*gate)
            loc += e[u];
        }
#pragma unroll
        for (int o = 16; o; o >>= 1) loc += __shfl_xor_sync(0xffffffffu, loc, o);
        if (lane == 0) ps[r & 1][w] = loc;
        __syncthreads();
        float inv = frcp(ps[r & 1][0] + ps[r & 1][1] + ps[r & 1][2] + ps[r & 1][3]);

        float* orow = out + ((size_t)(b * DIM + i0 + r)) * DIM;
#pragma unroll
        for (int u = 0; u < 8; u++) orow[u * 128 + tid] = e[u] * inv;
    }
}

extern "C" void kernel_launch(void* const* d_in, const int* in_sizes, int n_in,
                              void* d_out, int out_size)
{
    const float* q  = (const float*)d_in[0];
    const float* k  = (const float*)d_in[1];
    // d_in[2] = v : unused by the reference
    const float* Wq = (const float*)d_in[3];
    const float* bq = (const float*)d_in[4];
    const float* Wk = (const float*)d_in[5];
    const float* bk = (const float*)d_in[6];
    const float* Wg = (const float*)d_in[7];
    const float* bg = (const float*)d_in[8];
    float* out = (float*)d_out;

    // qp, kp partials (both gemms in one grid for full-chip occupancy)
    gemm_part<<<dim3(16, KSPLIT, 2), 256>>>(0, q, k, Wq, Wk, Wg);
    w1s_kernel<<<128, 256>>>(Wg);
    reduce_part<<<dim3(BATCH * DIM / 256, 2), 256>>>(0, bq, bk);
    // g2 = kp @ W2^T + bg  (depends on kp)
    gemm_part<<<dim3(16, KSPLIT, 1), 256>>>(2, q, k, Wq, Wk, Wg);
    reduce_part<<<dim3(BATCH * DIM / 256, 1), 256>>>(2, bg, bg);
    // fused scores/gate/softmax, writes full 256 MB output in one pass
    fused_softmax<<<dim3(BATCH, DIM / 16), 128>>>(out);
}

// round 2
// speedup vs baseline: 1.1661x; 1.1661x over previous
#include <cuda_runtime.h>
#include <cstdint>

#define BATCH 64
#define DIM 1024
#define KSPLIT 16
#define KCHUNK 64   // DIM / KSPLIT
#define ROWS 32     // rows per fused block

// ---- scratch (device globals; no allocations allowed) ----
__device__ float g_part[3][KSPLIT][BATCH * DIM];  // split-K partials: 0=qp, 1=kp, 2=g2
__device__ float g_qp[BATCH * DIM];
__device__ float g_kp[BATCH * DIM];
__device__ float g_g2[BATCH * DIM];
__device__ float g_w1s[DIM];

typedef unsigned long long u64;

__device__ __forceinline__ float frcp(float x) {
    float r; asm("rcp.approx.f32 %0, %1;" : "=f"(r) : "f"(x)); return r;
}
__device__ __forceinline__ float fex2(float x) {
    float r; asm("ex2.approx.f32 %0, %1;" : "=f"(r) : "f"(x)); return r;
}
__device__ __forceinline__ float ftanh(float x) {
    float r; asm("tanh.approx.f32 %0, %1;" : "=f"(r) : "f"(x)); return r;
}
__device__ __forceinline__ u64 pk(float lo, float hi) {
    u64 d; asm("mov.b64 %0, {%1, %2};" : "=l"(d)
               : "r"(__float_as_uint(lo)), "r"(__float_as_uint(hi)));
    return d;
}
__device__ __forceinline__ void upk(float& lo, float& hi, u64 d) {
    unsigned a, b;
    asm("mov.b64 {%0, %1}, %2;" : "=r"(a), "=r"(b) : "l"(d));
    lo = __uint_as_float(a); hi = __uint_as_float(b);
}
__device__ __forceinline__ u64 fma2(u64 a, u64 b, u64 c) {
    u64 d; asm("fma.rn.f32x2 %0, %1, %2, %3;" : "=l"(d) : "l"(a), "l"(b), "l"(c));
    return d;
}
__device__ __forceinline__ u64 mul2(u64 a, u64 b) {
    u64 d; asm("mul.rn.f32x2 %0, %1, %2;" : "=l"(d) : "l"(a), "l"(b));
    return d;
}
__device__ __forceinline__ u64 add2(u64 a, u64 b) {
    u64 d; asm("add.rn.f32x2 %0, %1, %2;" : "=l"(d) : "l"(a), "l"(b));
    return d;
}

// ---------------------------------------------------------------------------
// Split-K GEMM partials with register prefetch.
// sel 0: qp = q @ Wq^T   sel 1: kp = k @ Wk^T   sel 2: g2 = kp @ W2^T
// Tile: 64(M) x 64(N) x KCHUNK=64. grid = (16, KSPLIT, ngemm)
// ---------------------------------------------------------------------------
__global__ __launch_bounds__(256) void gemm_part(
    int sel_base,
    const float* __restrict__ q, const float* __restrict__ k,
    const float* __restrict__ Wq, const float* __restrict__ Wk,
    const float* __restrict__ Wg)
{
    int sel = sel_base + blockIdx.z;
    const float* in;
    const float* W;
    int ld, off;
    if (sel == 0)      { in = q;    W = Wq; ld = DIM;     off = 0;   }
    else if (sel == 1) { in = k;    W = Wk; ld = DIM;     off = 0;   }
    else               { in = g_kp; W = Wg; ld = 2 * DIM; off = DIM; }
    float* part = &g_part[sel][blockIdx.y][0];

    const int o0 = blockIdx.x * 64;
    const int k0 = blockIdx.y * KCHUNK;

    __shared__ __align__(16) float As[32][68];  // [k][m]
    __shared__ __align__(16) float Bs[32][68];  // [k][n]

    const int t  = threadIdx.x;
    const int tx = t & 15;   // n / 4
    const int ty = t >> 4;   // m / 4
    const int m0 = t >> 3;   // 0..31 (row for loads)
    const int kq = t & 7;    // 0..7  (k quad)

    float acc[4][4];
#pragma unroll
    for (int i = 0; i < 4; i++)
#pragma unroll
        for (int j = 0; j < 4; j++) acc[i][j] = 0.f;

    // prefetch kc=0 into registers
    float4 va0, va1, vb0, vb1;
    {
        const float* ain = &in[k0 + kq * 4];
        const float* win = &W[(size_t)(o0)*ld + off + k0 + kq * 4];
        va0 = *reinterpret_cast<const float4*>(&ain[(size_t)m0 * DIM]);
        va1 = *reinterpret_cast<const float4*>(&ain[(size_t)(m0 + 32) * DIM]);
        vb0 = *reinterpret_cast<const float4*>(&win[(size_t)m0 * ld]);
        vb1 = *reinterpret_cast<const float4*>(&win[(size_t)(m0 + 32) * ld]);
    }

#pragma unroll
    for (int kc = 0; kc < KCHUNK; kc += 32) {
        if (kc) __syncthreads();
        As[kq * 4 + 0][m0] = va0.x; As[kq * 4 + 1][m0] = va0.y;
        As[kq * 4 + 2][m0] = va0.z; As[kq * 4 + 3][m0] = va0.w;
        As[kq * 4 + 0][m0 + 32] = va1.x; As[kq * 4 + 1][m0 + 32] = va1.y;
        As[kq * 4 + 2][m0 + 32] = va1.z; As[kq * 4 + 3][m0 + 32] = va1.w;
        Bs[kq * 4 + 0][m0] = vb0.x; Bs[kq * 4 + 1][m0] = vb0.y;
        Bs[kq * 4 + 2][m0] = vb0.z; Bs[kq * 4 + 3][m0] = vb0.w;
        Bs[kq * 4 + 0][m0 + 32] = vb1.x; Bs[kq * 4 + 1][m0 + 32] = vb1.y;
        Bs[kq * 4 + 2][m0 + 32] = vb1.z; Bs[kq * 4 + 3][m0 + 32] = vb1.w;
        __syncthreads();
        if (kc + 32 < KCHUNK) {
            const float* ain = &in[k0 + kc + 32 + kq * 4];
            const float* win = &W[(size_t)(o0)*ld + off + k0 + kc + 32 + kq * 4];
            va0 = *reinterpret_cast<const float4*>(&ain[(size_t)m0 * DIM]);
            va1 = *reinterpret_cast<const float4*>(&ain[(size_t)(m0 + 32) * DIM]);
            vb0 = *reinterpret_cast<const float4*>(&win[(size_t)m0 * ld]);
            vb1 = *reinterpret_cast<const float4*>(&win[(size_t)(m0 + 32) * ld]);
        }
#pragma unroll
        for (int kk = 0; kk < 32; kk++) {
            float4 a  = *reinterpret_cast<const float4*>(&As[kk][ty * 4]);
            float4 bv = *reinterpret_cast<const float4*>(&Bs[kk][tx * 4]);
            acc[0][0] = fmaf(a.x, bv.x, acc[0][0]);
            acc[0][1] = fmaf(a.x, bv.y, acc[0][1]);
            acc[0][2] = fmaf(a.x, bv.z, acc[0][2]);
            acc[0][3] = fmaf(a.x, bv.w, acc[0][3]);
            acc[1][0] = fmaf(a.y, bv.x, acc[1][0]);
            acc[1][1] = fmaf(a.y, bv.y, acc[1][1]);
            acc[1][2] = fmaf(a.y, bv.z, acc[1][2]);
            acc[1][3] = fmaf(a.y, bv.w, acc[1][3]);
            acc[2][0] = fmaf(a.z, bv.x, acc[2][0]);
            acc[2][1] = fmaf(a.z, bv.y, acc[2][1]);
            acc[2][2] = fmaf(a.z, bv.z, acc[2][2]);
            acc[2][3] = fmaf(a.z, bv.w, acc[2][3]);
            acc[3][0] = fmaf(a.w, bv.x, acc[3][0]);
            acc[3][1] = fmaf(a.w, bv.y, acc[3][1]);
            acc[3][2] = fmaf(a.w, bv.z, acc[3][2]);
            acc[3][3] = fmaf(a.w, bv.w, acc[3][3]);
        }
    }

#pragma unroll
    for (int i = 0; i < 4; i++) {
        float4 v = make_float4(acc[i][0], acc[i][1], acc[i][2], acc[i][3]);
        *reinterpret_cast<float4*>(&part[(ty * 4 + i) * DIM + o0 + tx * 4]) = v;
    }
}

// reduce split-K partials for qp & kp + compute w1s. grid = 384 x 256
__global__ __launch_bounds__(256) void reduce_qk_w1s(
    const float* __restrict__ bq, const float* __restrict__ bk,
    const float* __restrict__ Wg)
{
    if (blockIdx.x < 256) {
        int idx = blockIdx.x * 256 + threadIdx.x;
        float s0 = bq[idx & (DIM - 1)];
        float s1 = bk[idx & (DIM - 1)];
#pragma unroll
        for (int sp = 0; sp < KSPLIT; sp++) {
            s0 += g_part[0][sp][idx];
            s1 += g_part[1][sp][idx];
        }
        g_qp[idx] = s0;
        g_kp[idx] = s1;
    } else {
        int gw   = (blockIdx.x - 256) * 8 + (threadIdx.x >> 5);
        int lane = threadIdx.x & 31;
        const float* row = Wg + (size_t)gw * (2 * DIM);
        float s = 0.f;
#pragma unroll
        for (int i = 0; i < 8; i++) {
            float4 v = *reinterpret_cast<const float4*>(&row[lane * 4 + i * 128]);
            s += v.x + v.y + v.z + v.w;
        }
#pragma unroll
        for (int o = 16; o; o >>= 1) s += __shfl_xor_sync(0xffffffffu, s, o);
        if (lane == 0) g_w1s[gw] = s;
    }
}

// reduce g2 partials. grid = 256 x 256
__global__ __launch_bounds__(256) void reduce_g2(const float* __restrict__ bg)
{
    int idx = blockIdx.x * 256 + threadIdx.x;
    float s = bg[idx & (DIM - 1)];
#pragma unroll
    for (int sp = 0; sp < KSPLIT; sp++) s += g_part[2][sp][idx];
    g_g2[idx] = s;
}

// ---------------------------------------------------------------------------
// Fused scores*gate + softmax, single pass over the 256 MB output.
//   x[b,i,j] = qp[b,i]*kp[b,j] * sig(sig(qp[b,i]*w1s[j] + g2[b,j]))
// inner sigmoid: 0.5 + 0.5*tanh(t/2)  (HW tanh.approx, 1 MUFU)
// outer sigmoid: arg in (0,1) -> odd Taylor deg-7 (err <= 2.1e-5), f32x2 packed
// exp: ex2.approx of score*gate*log2e.  Max-subtraction provably unneeded.
// Thread t owns j = 4t..4t+3 (pairs packed in b64); 32 rows per block.
// ---------------------------------------------------------------------------
__global__ __launch_bounds__(256) void fused_softmax(
    float* __restrict__ out, const float* __restrict__ unused)
{
    const int b   = blockIdx.x;
    const int i0  = blockIdx.y * ROWS;
    const int tid = threadIdx.x;
    const int j0  = tid * 4;

    __shared__ float qs[ROWS];
    __shared__ float ps[2][8];

    const float L2E = 1.4426950408889634f;
    const float C1 = 0.25f, C3 = -1.0f / 48.0f, C5 = 1.0f / 480.0f, C7 = -17.0f / 80640.0f;
    const u64 C1p = pk(C1, C1), C3p = pk(C3, C3), C5p = pk(C5, C5), C7p = pk(C7, C7);
    const u64 HALFp = pk(0.5f, 0.5f);

    // per-j coefficients, packed into b64 pairs
    float4 kpv = *reinterpret_cast<const float4*>(&g_kp[b * DIM + j0]);
    float4 wv  = *reinterpret_cast<const float4*>(&g_w1s[j0]);
    float4 gv  = *reinterpret_cast<const float4*>(&g_g2[b * DIM + j0]);
    u64 ap0 = pk(kpv.x * L2E, kpv.y * L2E);
    u64 ap1 = pk(kpv.z * L2E, kpv.w * L2E);
    u64 cw0 = pk(wv.x * 0.5f, wv.y * 0.5f);
    u64 cw1 = pk(wv.z * 0.5f, wv.w * 0.5f);
    u64 cg0 = pk(gv.x * 0.5f, gv.y * 0.5f);
    u64 cg1 = pk(gv.z * 0.5f, gv.w * 0.5f);

    if (tid < ROWS) qs[tid] = g_qp[b * DIM + i0 + tid];
    __syncthreads();

    const int w = tid >> 5, lane = tid & 31;
    float* oblk = out + ((size_t)(b * DIM + i0)) * DIM + j0;

#pragma unroll 1
    for (int r = 0; r < ROWS; r++) {
        const float qi = qs[r];
        const u64 qip = pk(qi, qi);

        u64 ep[2];
#pragma unroll
        for (int p = 0; p < 2; p++) {
            const u64 cwp = p ? cw1 : cw0;
            const u64 cgp = p ? cg1 : cg0;
            const u64 app = p ? ap1 : ap0;
            // gate_pre/2 for both lanes
            u64 argp = fma2(qip, cwp, cgp);
            float a0, a1; upk(a0, a1, argp);
            float th0 = ftanh(a0), th1 = ftanh(a1);
            u64 s1p = fma2(pk(th0, th1), HALFp, HALFp);   // inner sigmoid
            u64 z2  = mul2(s1p, s1p);                     // outer sigmoid poly
            u64 pp  = fma2(z2, C7p, C5p);
            pp      = fma2(z2, pp, C3p);
            pp      = fma2(z2, pp, C1p);
            u64 gatep = fma2(s1p, pp, HALFp);
            u64 eargp = mul2(mul2(qip, app), gatep);      // score*gate*log2e
            float e0a, e1a; upk(e0a, e1a, eargp);
            ep[p] = pk(fex2(e0a), fex2(e1a));
        }
        // row sum
        float lo, hi; upk(lo, hi, add2(ep[0], ep[1]));
        float loc = lo + hi;
#pragma unroll
        for (int o = 16; o; o >>= 1) loc += __shfl_xor_sync(0xffffffffu, loc, o);
        if (lane == 0) ps[r & 1][w] = loc;
        __syncthreads();
        float tot = 0.f;
#pragma unroll
        for (int ww = 0; ww < 8; ww++) tot += ps[r & 1][ww];
        float inv = frcp(tot);
        u64 invp = pk(inv, inv);

        u64 o0 = mul2(ep[0], invp);
        u64 o1 = mul2(ep[1], invp);
        // 128-bit streaming store, evict-first (output is write-once)
        asm volatile("st.global.cs.v2.b64 [%0], {%1, %2};"
                     :: "l"(oblk + (size_t)r * DIM), "l"(o0), "l"(o1) : "memory");
    }
}

extern "C" void kernel_launch(void* const* d_in, const int* in_sizes, int n_in,
                              void* d_out, int out_size)
{
    const float* q  = (const float*)d_in[0];
    const float* k  = (const float*)d_in[1];
    // d_in[2] = v : unused by the reference
    const float* Wq = (const float*)d_in[3];
    const float* bq = (const float*)d_in[4];
    const float* Wk = (const float*)d_in[5];
    const float* bk = (const float*)d_in[6];
    const float* Wg = (const float*)d_in[7];
    const float* bg = (const float*)d_in[8];
    float* out = (float*)d_out;

    // L1: qp & kp split-K partials (both gemms in one grid)
    gemm_part<<<dim3(16, KSPLIT, 2), 256>>>(0, q, k, Wq, Wk, Wg);
    // L2: reduce qp,kp + w1s row sums
    reduce_qk_w1s<<<384, 256>>>(bq, bk, Wg);
    // L3: g2 = kp @ W2^T partials
    gemm_part<<<dim3(16, KSPLIT, 1), 256>>>(2, q, k, Wq, Wk, Wg);
    // L4: reduce g2 (+bg)
    reduce_g2<<<256, 256>>>(bg);
    // L5: fused scores/gate/softmax — one pass over 256 MB output
    fused_softmax<<<dim3(BATCH, DIM / ROWS), 256>>>(out, bg);
}

// round 4
// speedup vs baseline: 1.2202x; 1.0464x over previous
#include <cuda_runtime.h>
#include <cstdint>

#define BATCH 64
#define DIM 1024
#define ROWS 32     // rows per fused block

// ---- scratch (device globals; no allocations allowed) ----
__device__ float g_qp[BATCH * DIM];
__device__ float g_kp[BATCH * DIM];
__device__ float g_g2[BATCH * DIM];
__device__ float g_w1s[DIM];

typedef unsigned long long u64;

__device__ __forceinline__ float frcp(float x) {
    float r; asm("rcp.approx.f32 %0, %1;" : "=f"(r) : "f"(x)); return r;
}
__device__ __forceinline__ float fex2(float x) {
    float r; asm("ex2.approx.f32 %0, %1;" : "=f"(r) : "f"(x)); return r;
}
__device__ __forceinline__ float ftanh(float x) {
    float r; asm("tanh.approx.f32 %0, %1;" : "=f"(r) : "f"(x)); return r;
}
__device__ __forceinline__ u64 pk(float lo, float hi) {
    u64 d; asm("mov.b64 %0, {%1, %2};" : "=l"(d)
               : "r"(__float_as_uint(lo)), "r"(__float_as_uint(hi)));
    return d;
}
__device__ __forceinline__ void upk(float& lo, float& hi, u64 d) {
    unsigned a, b;
    asm("mov.b64 {%0, %1}, %2;" : "=r"(a), "=r"(b) : "l"(d));
    lo = __uint_as_float(a); hi = __uint_as_float(b);
}
__device__ __forceinline__ u64 fma2(u64 a, u64 b, u64 c) {
    u64 d; asm("fma.rn.f32x2 %0, %1, %2, %3;" : "=l"(d) : "l"(a), "l"(b), "l"(c));
    return d;
}
__device__ __forceinline__ u64 mul2(u64 a, u64 b) {
    u64 d; asm("mul.rn.f32x2 %0, %1, %2;" : "=l"(d) : "l"(a), "l"(b));
    return d;
}
__device__ __forceinline__ u64 add2(u64 a, u64 b) {
    u64 d; asm("add.rn.f32x2 %0, %1, %2;" : "=l"(d) : "l"(a), "l"(b));
    return d;
}
__device__ __forceinline__ void red4(float* addr, float a, float b, float c, float d) {
    asm volatile("red.global.v4.f32.add [%0], {%1, %2, %3, %4};"
                 :: "l"(addr), "f"(a), "f"(b), "f"(c), "f"(d) : "memory");
}

// ---------------------------------------------------------------------------
// L0: zero accumulators + w1s row sums.  grid = 320 x 256
//   blocks [0,192): zero g_qp/g_kp/g_g2 (49152 float4 total)
//   blocks [192,320): w1s[j] = sum_c Wg[j, c<DIM], one warp per row
// ---------------------------------------------------------------------------
__global__ __launch_bounds__(256) void init_kernel(const float* __restrict__ Wg)
{
    int bid = blockIdx.x;
    if (bid < 192) {
        int idx = bid * 256 + threadIdx.x;           // 0..49151
        float* arr = (idx < 16384) ? g_qp : (idx < 32768) ? g_kp : g_g2;
        *reinterpret_cast<float4*>(arr + (size_t)(idx & 16383) * 4) =
            make_float4(0.f, 0.f, 0.f, 0.f);
    } else {
        int gw   = (bid - 192) * 8 + (threadIdx.x >> 5);  // 0..1023
        int lane = threadIdx.x & 31;
        const float* row = Wg + (size_t)gw * (2 * DIM);
        float s = 0.f;
#pragma unroll
        for (int i = 0; i < 8; i++) {
            float4 v = *reinterpret_cast<const float4*>(&row[lane * 4 + i * 128]);
            s += v.x + v.y + v.z + v.w;
        }
#pragma unroll
        for (int o = 16; o; o >>= 1) s += __shfl_xor_sync(0xffffffffu, s, o);
        if (lane == 0) g_w1s[gw] = s;
    }
}

// ---------------------------------------------------------------------------
// Split-K GEMM, atomic accumulation into final buffer (no reduce pass).
// sel 0: qp += q @ Wq^T (+bq on split 0)   sel 1: kp = k @ Wk^T (+bk)
// sel 2: g2 = kp @ W2^T (+bg)
// Tile 64(M) x 64(N); K-chunk = DIM / gridDim.y.  grid = (16, KSPLIT, ngemm)
// ---------------------------------------------------------------------------
__global__ __launch_bounds__(256) void gemm_atom(
    int sel_base,
    const float* __restrict__ q, const float* __restrict__ k,
    const float* __restrict__ Wq, const float* __restrict__ Wk,
    const float* __restrict__ Wg,
    const float* __restrict__ bq, const float* __restrict__ bk,
    const float* __restrict__ bg)
{
    int sel = sel_base + blockIdx.z;
    const float* in;
    const float* W;
    const float* bias;
    float* dst;
    int ld, off;
    if (sel == 0)      { in = q;    W = Wq; ld = DIM;     off = 0;   dst = g_qp; bias = bq; }
    else if (sel == 1) { in = k;    W = Wk; ld = DIM;     off = 0;   dst = g_kp; bias = bk; }
    else               { in = g_kp; W = Wg; ld = 2 * DIM; off = DIM; dst = g_g2; bias = bg; }

    const int kchunk = DIM / gridDim.y;
    const int o0 = blockIdx.x * 64;
    const int k0 = blockIdx.y * kchunk;

    __shared__ __align__(16) float As[32][68];  // [k][m]
    __shared__ __align__(16) float Bs[32][68];  // [k][n]

    const int t  = threadIdx.x;
    const int tx = t & 15;   // n / 4
    const int ty = t >> 4;   // m / 4
    const int m0 = t >> 3;   // 0..31
    const int kq = t & 7;    // 0..7

    float acc[4][4];
#pragma unroll
    for (int i = 0; i < 4; i++)
#pragma unroll
        for (int j = 0; j < 4; j++) acc[i][j] = 0.f;

    // prefetch first chunk
    float4 va0, va1, vb0, vb1;
    {
        const float* ain = &in[k0 + kq * 4];
        const float* win = &W[(size_t)o0 * ld + off + k0 + kq * 4];
        va0 = *reinterpret_cast<const float4*>(&ain[(size_t)m0 * DIM]);
        va1 = *reinterpret_cast<const float4*>(&ain[(size_t)(m0 + 32) * DIM]);
        vb0 = *reinterpret_cast<const float4*>(&win[(size_t)m0 * ld]);
        vb1 = *reinterpret_cast<const float4*>(&win[(size_t)(m0 + 32) * ld]);
    }

    for (int kc = 0; kc < kchunk; kc += 32) {
        if (kc) __syncthreads();
        As[kq * 4 + 0][m0] = va0.x; As[kq * 4 + 1][m0] = va0.y;
        As[kq * 4 + 2][m0] = va0.z; As[kq * 4 + 3][m0] = va0.w;
        As[kq * 4 + 0][m0 + 32] = va1.x; As[kq * 4 + 1][m0 + 32] = va1.y;
        As[kq * 4 + 2][m0 + 32] = va1.z; As[kq * 4 + 3][m0 + 32] = va1.w;
        Bs[kq * 4 + 0][m0] = vb0.x; Bs[kq * 4 + 1][m0] = vb0.y;
        Bs[kq * 4 + 2][m0] = vb0.z; Bs[kq * 4 + 3][m0] = vb0.w;
        Bs[kq * 4 + 0][m0 + 32] = vb1.x; Bs[kq * 4 + 1][m0 + 32] = vb1.y;
        Bs[kq * 4 + 2][m0 + 32] = vb1.z; Bs[kq * 4 + 3][m0 + 32] = vb1.w;
        __syncthreads();
        if (kc + 32 < kchunk) {
            const float* ain = &in[k0 + kc + 32 + kq * 4];
            const float* win = &W[(size_t)o0 * ld + off + k0 + kc + 32 + kq * 4];
            va0 = *reinterpret_cast<const float4*>(&ain[(size_t)m0 * DIM]);
            va1 = *reinterpret_cast<const float4*>(&ain[(size_t)(m0 + 32) * DIM]);
            vb0 = *reinterpret_cast<const float4*>(&win[(size_t)m0 * ld]);
            vb1 = *reinterpret_cast<const float4*>(&win[(size_t)(m0 + 32) * ld]);
        }
#pragma unroll
        for (int kk = 0; kk < 32; kk++) {
            float4 a  = *reinterpret_cast<const float4*>(&As[kk][ty * 4]);
            float4 bv = *reinterpret_cast<const float4*>(&Bs[kk][tx * 4]);
            acc[0][0] = fmaf(a.x, bv.x, acc[0][0]);
            acc[0][1] = fmaf(a.x, bv.y, acc[0][1]);
            acc[0][2] = fmaf(a.x, bv.z, acc[0][2]);
            acc[0][3] = fmaf(a.x, bv.w, acc[0][3]);
            acc[1][0] = fmaf(a.y, bv.x, acc[1][0]);
            acc[1][1] = fmaf(a.y, bv.y, acc[1][1]);
            acc[1][2] = fmaf(a.y, bv.z, acc[1][2]);
            acc[1][3] = fmaf(a.y, bv.w, acc[1][3]);
            acc[2][0] = fmaf(a.z, bv.x, acc[2][0]);
            acc[2][1] = fmaf(a.z, bv.y, acc[2][1]);
            acc[2][2] = fmaf(a.z, bv.z, acc[2][2]);
            acc[2][3] = fmaf(a.z, bv.w, acc[2][3]);
            acc[3][0] = fmaf(a.w, bv.x, acc[3][0]);
            acc[3][1] = fmaf(a.w, bv.y, acc[3][1]);
            acc[3][2] = fmaf(a.w, bv.z, acc[3][2]);
            acc[3][3] = fmaf(a.w, bv.w, acc[3][3]);
        }
    }

    // split 0 carries the bias
    if (blockIdx.y == 0) {
        float b0 = bias[o0 + tx * 4 + 0];
        float b1 = bias[o0 + tx * 4 + 1];
        float b2 = bias[o0 + tx * 4 + 2];
        float b3 = bias[o0 + tx * 4 + 3];
#pragma unroll
        for (int i = 0; i < 4; i++) {
            acc[i][0] += b0; acc[i][1] += b1; acc[i][2] += b2; acc[i][3] += b3;
        }
    }

#pragma unroll
    for (int i = 0; i < 4; i++)
        red4(&dst[(ty * 4 + i) * DIM + o0 + tx * 4],
             acc[i][0], acc[i][1], acc[i][2], acc[i][3]);
}

// ---------------------------------------------------------------------------
// Fused scores*gate + softmax, single pass over the 256 MB output.
//   x[b,i,j] = qp[b,i]*kp[b,j] * sig(sig(qp[b,i]*w1s[j] + g2[b,j]))
// inner sigmoid: 0.5 + 0.5*tanh(t/2)  (HW tanh.approx)
// outer sigmoid: arg in (0,1) -> odd Taylor deg-7, all math f32x2 packed
// 4 rows per barrier (double-buffered partial sums), 32 rows per block.
// ---------------------------------------------------------------------------
__global__ __launch_bounds__(256) void fused_softmax(float* __restrict__ out)
{
    const int b   = blockIdx.x;
    const int i0  = blockIdx.y * ROWS;
    const int tid = threadIdx.x;
    const int j0  = tid * 4;

    __shared__ float qs[ROWS];
    __shared__ float ps[2][4][8];

    const float L2E = 1.4426950408889634f;
    const float C1 = 0.25f, C3 = -1.0f / 48.0f, C5 = 1.0f / 480.0f, C7 = -17.0f / 80640.0f;
    const u64 C1p = pk(C1, C1), C3p = pk(C3, C3), C5p = pk(C5, C5), C7p = pk(C7, C7);
    const u64 HALFp = pk(0.5f, 0.5f);

    float4 kpv = *reinterpret_cast<const float4*>(&g_kp[b * DIM + j0]);
    float4 wv  = *reinterpret_cast<const float4*>(&g_w1s[j0]);
    float4 gv  = *reinterpret_cast<const float4*>(&g_g2[b * DIM + j0]);
    u64 ap0 = pk(kpv.x * L2E, kpv.y * L2E);
    u64 ap1 = pk(kpv.z * L2E, kpv.w * L2E);
    u64 cw0 = pk(wv.x * 0.5f, wv.y * 0.5f);
    u64 cw1 = pk(wv.z * 0.5f, wv.w * 0.5f);
    u64 cg0 = pk(gv.x * 0.5f, gv.y * 0.5f);
    u64 cg1 = pk(gv.z * 0.5f, gv.w * 0.5f);

    if (tid < ROWS) qs[tid] = g_qp[b * DIM + i0 + tid];
    __syncthreads();

    const int w = tid >> 5, lane = tid & 31;
    float* oblk = out + ((size_t)(b * DIM + i0)) * DIM + j0;

#pragma unroll 1
    for (int r0 = 0; r0 < ROWS; r0 += 4) {
        const int buf = (r0 >> 2) & 1;
        u64 ep[4][2];
#pragma unroll
        for (int rr = 0; rr < 4; rr++) {
            const float qi = qs[r0 + rr];
            const u64 qip = pk(qi, qi);
            const u64 qa0 = mul2(qip, ap0);
            const u64 qa1 = mul2(qip, ap1);
#pragma unroll
            for (int p = 0; p < 2; p++) {
                const u64 cwp = p ? cw1 : cw0;
                const u64 cgp = p ? cg1 : cg0;
                const u64 qap = p ? qa1 : qa0;
                u64 argp = fma2(qip, cwp, cgp);            // gate_pre / 2
                float a0, a1; upk(a0, a1, argp);
                float th0 = ftanh(a0), th1 = ftanh(a1);
                u64 s1p = fma2(pk(th0, th1), HALFp, HALFp);  // inner sigmoid
                u64 z2  = mul2(s1p, s1p);
                u64 pp  = fma2(z2, C7p, C5p);
                pp      = fma2(z2, pp, C3p);
                pp      = fma2(z2, pp, C1p);
                u64 gatep = fma2(s1p, pp, HALFp);            // outer sigmoid
                u64 eargp = mul2(qap, gatep);                // L2E*score*gate
                float e0a, e1a; upk(e0a, e1a, eargp);
                ep[rr][p] = pk(fex2(e0a), fex2(e1a));
            }
            float lo, hi; upk(lo, hi, add2(ep[rr][0], ep[rr][1]));
            float loc = lo + hi;
#pragma unroll
            for (int o = 16; o; o >>= 1) loc += __shfl_xor_sync(0xffffffffu, loc, o);
            if (lane == 0) ps[buf][rr][w] = loc;
        }
        __syncthreads();
#pragma unroll
        for (int rr = 0; rr < 4; rr++) {
            float v = ps[buf][rr][lane & 7];       // broadcast LDS, conflict-free
            v += __shfl_xor_sync(0xffffffffu, v, 1);
            v += __shfl_xor_sync(0xffffffffu, v, 2);
            v += __shfl_xor_sync(0xffffffffu, v, 4);
            float inv = frcp(v);
            u64 invp = pk(inv, inv);
            u64 o0v = mul2(ep[rr][0], invp);
            u64 o1v = mul2(ep[rr][1], invp);
            asm volatile("st.global.cs.v2.b64 [%0], {%1, %2};"
                         :: "l"(oblk + (size_t)(r0 + rr) * DIM), "l"(o0v), "l"(o1v)
                         : "memory");
        }
    }
}

extern "C" void kernel_launch(void* const* d_in, const int* in_sizes, int n_in,
                              void* d_out, int out_size)
{
    const float* q  = (const float*)d_in[0];
    const float* k  = (const float*)d_in[1];
    // d_in[2] = v : unused by the reference
    const float* Wq = (const float*)d_in[3];
    const float* bq = (const float*)d_in[4];
    const float* Wk = (const float*)d_in[5];
    const float* bk = (const float*)d_in[6];
    const float* Wg = (const float*)d_in[7];
    const float* bg = (const float*)d_in[8];
    float* out = (float*)d_out;

    // L0: zero accumulators + w1s
    init_kernel<<<320, 256>>>(Wg);
    // L1: qp & kp (atomic split-K, KSPLIT=8)
    gemm_atom<<<dim3(16, 8, 2), 256>>>(0, q, k, Wq, Wk, Wg, bq, bk, bg);
    // L2: g2 = kp @ W2^T (atomic split-K, KSPLIT=16 — on the critical path)
    gemm_atom<<<dim3(16, 16, 1), 256>>>(2, q, k, Wq, Wk, Wg, bq, bk, bg);
    // L3: fused scores/gate/softmax — one pass over the 256 MB output
    fused_softmax<<<dim3(BATCH, DIM / ROWS), 256>>>(out);
}

// round 6
// speedup vs baseline: 1.2225x; 1.0019x over previous
#include <cuda_runtime.h>
#include <cstdint>

#define BATCH 64
#define DIM 1024
#define ROWS 32     // rows per fused block

// ---- scratch (device globals; no allocations allowed) ----
__device__ float g_qp[BATCH * DIM];
__device__ float g_kp[BATCH * DIM];
__device__ float g_g2[BATCH * DIM];
__device__ float g_w1s[DIM];

typedef unsigned long long u64;

__device__ __forceinline__ float frcp(float x) {
    float r; asm("rcp.approx.f32 %0, %1;" : "=f"(r) : "f"(x)); return r;
}
__device__ __forceinline__ float fex2(float x) {
    float r; asm("ex2.approx.f32 %0, %1;" : "=f"(r) : "f"(x)); return r;
}
__device__ __forceinline__ float ftanh(float x) {
    float r; asm("tanh.approx.f32 %0, %1;" : "=f"(r) : "f"(x)); return r;
}
__device__ __forceinline__ u64 pk(float lo, float hi) {
    u64 d; asm("mov.b64 %0, {%1, %2};" : "=l"(d)
               : "r"(__float_as_uint(lo)), "r"(__float_as_uint(hi)));
    return d;
}
__device__ __forceinline__ void upk(float& lo, float& hi, u64 d) {
    unsigned a, b;
    asm("mov.b64 {%0, %1}, %2;" : "=r"(a), "=r"(b) : "l"(d));
    lo = __uint_as_float(a); hi = __uint_as_float(b);
}
__device__ __forceinline__ u64 fma2(u64 a, u64 b, u64 c) {
    u64 d; asm("fma.rn.f32x2 %0, %1, %2, %3;" : "=l"(d) : "l"(a), "l"(b), "l"(c));
    return d;
}
__device__ __forceinline__ u64 mul2(u64 a, u64 b) {
    u64 d; asm("mul.rn.f32x2 %0, %1, %2;" : "=l"(d) : "l"(a), "l"(b));
    return d;
}
__device__ __forceinline__ void red4(float* addr, float a, float b, float c, float d) {
    asm volatile("red.global.v4.f32.add [%0], {%1, %2, %3, %4};"
                 :: "l"(addr), "f"(a), "f"(b), "f"(c), "f"(d) : "memory");
}

// ---------------------------------------------------------------------------
// L0: zero accumulators + w1s row sums.  grid = 320 x 256
// ---------------------------------------------------------------------------
__global__ __launch_bounds__(256) void init_kernel(const float* __restrict__ Wg)
{
    int bid = blockIdx.x;
    if (bid < 192) {
        int idx = bid * 256 + threadIdx.x;           // 0..49151
        float* arr = (idx < 16384) ? g_qp : (idx < 32768) ? g_kp : g_g2;
        *reinterpret_cast<float4*>(arr + (size_t)(idx & 16383) * 4) =
            make_float4(0.f, 0.f, 0.f, 0.f);
    } else {
        int gw   = (bid - 192) * 8 + (threadIdx.x >> 5);  // 0..1023
        int lane = threadIdx.x & 31;
        const float* row = Wg + (size_t)gw * (2 * DIM);
        float s = 0.f;
#pragma unroll
        for (int i = 0; i < 8; i++) {
            float4 v = *reinterpret_cast<const float4*>(&row[lane * 4 + i * 128]);
            s += v.x + v.y + v.z + v.w;
        }
#pragma unroll
        for (int o = 16; o; o >>= 1) s += __shfl_xor_sync(0xffffffffu, s, o);
        if (lane == 0) g_w1s[gw] = s;
    }
}

// ---------------------------------------------------------------------------
// Split-K GEMM, atomic accumulation into final buffer (no reduce pass).
// sel 0: qp = q @ Wq^T (+bq)   sel 1: kp = k @ Wk^T (+bk)   sel 2: g2 = kp @ W2^T (+bg)
// Tile 64(M) x 64(N); K-chunk = DIM / gridDim.y.
// ---------------------------------------------------------------------------
__global__ __launch_bounds__(256) void gemm_atom(
    int sel_base,
    const float* __restrict__ q, const float* __restrict__ k,
    const float* __restrict__ Wq, const float* __restrict__ Wk,
    const float* __restrict__ Wg,
    const float* __restrict__ bq, const float* __restrict__ bk,
    const float* __restrict__ bg)
{
    int sel = sel_base + blockIdx.z;
    const float* in;
    const float* W;
    const float* bias;
    float* dst;
    int ld, off;
    if (sel == 0)      { in = q;    W = Wq; ld = DIM;     off = 0;   dst = g_qp; bias = bq; }
    else if (sel == 1) { in = k;    W = Wk; ld = DIM;     off = 0;   dst = g_kp; bias = bk; }
    else               { in = g_kp; W = Wg; ld = 2 * DIM; off = DIM; dst = g_g2; bias = bg; }

    const int kchunk = DIM / gridDim.y;
    const int o0 = blockIdx.x * 64;
    const int k0 = blockIdx.y * kchunk;

    __shared__ __align__(16) float As[32][68];  // [k][m]
    __shared__ __align__(16) float Bs[32][68];  // [k][n]

    const int t  = threadIdx.x;
    const int tx = t & 15;   // n / 4
    const int ty = t >> 4;   // m / 4
    const int m0 = t >> 3;   // 0..31
    const int kq = t & 7;    // 0..7

    float acc[4][4];
#pragma unroll
    for (int i = 0; i < 4; i++)
#pragma unroll
        for (int j = 0; j < 4; j++) acc[i][j] = 0.f;

    // prefetch first chunk
    float4 va0, va1, vb0, vb1;
    {
        const float* ain = &in[k0 + kq * 4];
        const float* win = &W[(size_t)o0 * ld + off + k0 + kq * 4];
        va0 = *reinterpret_cast<const float4*>(&ain[(size_t)m0 * DIM]);
        va1 = *reinterpret_cast<const float4*>(&ain[(size_t)(m0 + 32) * DIM]);
        vb0 = *reinterpret_cast<const float4*>(&win[(size_t)m0 * ld]);
        vb1 = *reinterpret_cast<const float4*>(&win[(size_t)(m0 + 32) * ld]);
    }

    for (int kc = 0; kc < kchunk; kc += 32) {
        if (kc) __syncthreads();
        As[kq * 4 + 0][m0] = va0.x; As[kq * 4 + 1][m0] = va0.y;
        As[kq * 4 + 2][m0] = va0.z; As[kq * 4 + 3][m0] = va0.w;
        As[kq * 4 + 0][m0 + 32] = va1.x; As[kq * 4 + 1][m0 + 32] = va1.y;
        As[kq * 4 + 2][m0 + 32] = va1.z; As[kq * 4 + 3][m0 + 32] = va1.w;
        Bs[kq * 4 + 0][m0] = vb0.x; Bs[kq * 4 + 1][m0] = vb0.y;
        Bs[kq * 4 + 2][m0] = vb0.z; Bs[kq * 4 + 3][m0] = vb0.w;
        Bs[kq * 4 + 0][m0 + 32] = vb1.x; Bs[kq * 4 + 1][m0 + 32] = vb1.y;
        Bs[kq * 4 + 2][m0 + 32] = vb1.z; Bs[kq * 4 + 3][m0 + 32] = vb1.w;
        __syncthreads();
        if (kc + 32 < kchunk) {
            const float* ain = &in[k0 + kc + 32 + kq * 4];
            const float* win = &W[(size_t)o0 * ld + off + k0 + kc + 32 + kq * 4];
            va0 = *reinterpret_cast<const float4*>(&ain[(size_t)m0 * DIM]);
            va1 = *reinterpret_cast<const float4*>(&ain[(size_t)(m0 + 32) * DIM]);
            vb0 = *reinterpret_cast<const float4*>(&win[(size_t)m0 * ld]);
            vb1 = *reinterpret_cast<const float4*>(&win[(size_t)(m0 + 32) * ld]);
        }
#pragma unroll
        for (int kk = 0; kk < 32; kk++) {
            float4 a  = *reinterpret_cast<const float4*>(&As[kk][ty * 4]);
            float4 bv = *reinterpret_cast<const float4*>(&Bs[kk][tx * 4]);
            acc[0][0] = fmaf(a.x, bv.x, acc[0][0]);
            acc[0][1] = fmaf(a.x, bv.y, acc[0][1]);
            acc[0][2] = fmaf(a.x, bv.z, acc[0][2]);
            acc[0][3] = fmaf(a.x, bv.w, acc[0][3]);
            acc[1][0] = fmaf(a.y, bv.x, acc[1][0]);
            acc[1][1] = fmaf(a.y, bv.y, acc[1][1]);
            acc[1][2] = fmaf(a.y, bv.z, acc[1][2]);
            acc[1][3] = fmaf(a.y, bv.w, acc[1][3]);
            acc[2][0] = fmaf(a.z, bv.x, acc[2][0]);
            acc[2][1] = fmaf(a.z, bv.y, acc[2][1]);
            acc[2][2] = fmaf(a.z, bv.z, acc[2][2]);
            acc[2][3] = fmaf(a.z, bv.w, acc[2][3]);
            acc[3][0] = fmaf(a.w, bv.x, acc[3][0]);
            acc[3][1] = fmaf(a.w, bv.y, acc[3][1]);
            acc[3][2] = fmaf(a.w, bv.z, acc[3][2]);
            acc[3][3] = fmaf(a.w, bv.w, acc[3][3]);
        }
    }

    // split 0 carries the bias
    if (blockIdx.y == 0) {
        float b0 = bias[o0 + tx * 4 + 0];
        float b1 = bias[o0 + tx * 4 + 1];
        float b2 = bias[o0 + tx * 4 + 2];
        float b3 = bias[o0 + tx * 4 + 3];
#pragma unroll
        for (int i = 0; i < 4; i++) {
            acc[i][0] += b0; acc[i][1] += b1; acc[i][2] += b2; acc[i][3] += b3;
        }
    }

#pragma unroll
    for (int i = 0; i < 4; i++)
        red4(&dst[(ty * 4 + i) * DIM + o0 + tx * 4],
             acc[i][0], acc[i][1], acc[i][2], acc[i][3]);
}

// ---------------------------------------------------------------------------
// Fused scores*gate + softmax, single pass over the 256 MB output.
//   x[b,i,j] = qp[b,i]*kp[b,j] * sig(sig(qp[b,i]*w1s[j] + g2[b,j]))
// inner sigmoid: 0.5 + 0.5*tanh(t/2)  (HW tanh.approx)
// outer sigmoid: deg-5 MINIMAX odd poly in s1 over [-1,1] (err ~5e-6)
// row sums: 5-level shfl.bfly tree + cross-warp bcast-LDS + 3 shfl
// ---------------------------------------------------------------------------
__global__ __launch_bounds__(256) void fused_softmax(float* __restrict__ out)
{
    const int b   = blockIdx.x;
    const int i0  = blockIdx.y * ROWS;
    const int tid = threadIdx.x;
    const int j0  = tid * 4;

    __shared__ float qs[ROWS];
    __shared__ float ps[2][4][8];

    const float L2E = 1.4426950408889634f;
    // deg-5 minimax (Chebyshev-economized Taylor) for sigma(u)-0.5, u in [-1,1]
    const float A1 = 0.2499814f, A3 = -0.02068092f, A5 = 0.00176246f;
    const u64 A1p = pk(A1, A1), A3p = pk(A3, A3), A5p = pk(A5, A5);
    const u64 HALFp = pk(0.5f, 0.5f);

    float4 kpv = *reinterpret_cast<const float4*>(&g_kp[b * DIM + j0]);
    float4 wv  = *reinterpret_cast<const float4*>(&g_w1s[j0]);
    float4 gv  = *reinterpret_cast<const float4*>(&g_g2[b * DIM + j0]);
    u64 ap0 = pk(kpv.x * L2E, kpv.y * L2E);
    u64 ap1 = pk(kpv.z * L2E, kpv.w * L2E);
    u64 cw0 = pk(wv.x * 0.5f, wv.y * 0.5f);
    u64 cw1 = pk(wv.z * 0.5f, wv.w * 0.5f);
    u64 cg0 = pk(gv.x * 0.5f, gv.y * 0.5f);
    u64 cg1 = pk(gv.z * 0.5f, gv.w * 0.5f);

    if (tid < ROWS) qs[tid] = g_qp[b * DIM + i0 + tid];
    __syncthreads();

    const int w = tid >> 5, lane = tid & 31;
    float* oblk = out + ((size_t)(b * DIM + i0)) * DIM + j0;

#pragma unroll 1
    for (int r0 = 0; r0 < ROWS; r0 += 4) {
        const int buf = (r0 >> 2) & 1;
        float e[4][4];
#pragma unroll
        for (int rr = 0; rr < 4; rr++) {
            const float qi = qs[r0 + rr];
            const u64 qip = pk(qi, qi);
            float loc = 0.f;
#pragma unroll
            for (int p = 0; p < 2; p++) {
                const u64 cwp = p ? cw1 : cw0;
                const u64 cgp = p ? cg1 : cg0;
                const u64 qap = mul2(qip, p ? ap1 : ap0);
                u64 argp = fma2(qip, cwp, cgp);              // gate_pre / 2
                float a0, a1; upk(a0, a1, argp);
                float th0 = ftanh(a0), th1 = ftanh(a1);
                u64 s1p = fma2(pk(th0, th1), HALFp, HALFp);  // inner sigmoid
                u64 z2  = mul2(s1p, s1p);
                u64 pp  = fma2(z2, A5p, A3p);                // minimax deg-5
                pp      = fma2(z2, pp, A1p);
                u64 gatep = fma2(s1p, pp, HALFp);            // outer sigmoid
                u64 eargp = mul2(qap, gatep);                // L2E*score*gate
                float e0a, e1a; upk(e0a, e1a, eargp);
                float e0 = fex2(e0a), e1 = fex2(e1a);
                e[rr][2 * p]     = e0;
                e[rr][2 * p + 1] = e1;
                loc += e0; loc += e1;
            }
#pragma unroll
            for (int o = 16; o; o >>= 1) loc += __shfl_xor_sync(0xffffffffu, loc, o);
            if (lane == 0) ps[buf][rr][w] = loc;
        }
        __syncthreads();
#pragma unroll
        for (int rr = 0; rr < 4; rr++) {
            float v = ps[buf][rr][lane & 7];       // broadcast LDS, conflict-free
            v += __shfl_xor_sync(0xffffffffu, v, 1);
            v += __shfl_xor_sync(0xffffffffu, v, 2);
            v += __shfl_xor_sync(0xffffffffu, v, 4);
            float inv = frcp(v);
            float o0 = e[rr][0] * inv, o1 = e[rr][1] * inv;
            float o2 = e[rr][2] * inv, o3 = e[rr][3] * inv;
            asm volatile("st.global.cs.v4.f32 [%0], {%1, %2, %3, %4};"
                         :: "l"(oblk + (size_t)(r0 + rr) * DIM),
                            "f"(o0), "f"(o1), "f"(o2), "f"(o3) : "memory");
        }
    }
}

extern "C" void kernel_launch(void* const* d_in, const int* in_sizes, int n_in,
                              void* d_out, int out_size)
{
    const float* q  = (const float*)d_in[0];
    const float* k  = (const float*)d_in[1];
    // d_in[2] = v : unused by the reference
    const float* Wq = (const float*)d_in[3];
    const float* bq = (const float*)d_in[4];
    const float* Wk = (const float*)d_in[5];
    const float* bk = (const float*)d_in[6];
    const float* Wg = (const float*)d_in[7];
    const float* bg = (const float*)d_in[8];
    float* out = (float*)d_out;

    // L0: zero accumulators + w1s
    init_kernel<<<320, 256>>>(Wg);
    // L1: qp & kp (atomic split-K, KSPLIT=16 -> 512 blocks)
    gemm_atom<<<dim3(16, 16, 2), 256>>>(0, q, k, Wq, Wk, Wg, bq, bk, bg);
    // L2: g2 = kp @ W2^T (atomic split-K, KSPLIT=32 -> 512 blocks)
    gemm_atom<<<dim3(16, 32, 1), 256>>>(2, q, k, Wq, Wk, Wg, bq, bk, bg);
    // L3: fused scores/gate/softmax — one pass over the 256 MB output
    fused_softmax<<<dim3(BATCH, DIM / ROWS), 256>>>(out);
}

// round 8
// speedup vs baseline: 1.4747x; 1.2063x over previous
#include <cuda_runtime.h>
#include <cstdint>

#define BATCH 64
#define DIM 1024
#define ROWS 32     // rows per fused block

// ---- scratch (device globals; no allocations allowed) ----
__device__ float g_qp[BATCH * DIM];
__device__ float g_kp[BATCH * DIM];
__device__ float g_g2[BATCH * DIM];
__device__ float g_w1s[DIM];

typedef unsigned long long u64;

__device__ __forceinline__ float frcp(float x) {
    float r; asm("rcp.approx.f32 %0, %1;" : "=f"(r) : "f"(x)); return r;
}
__device__ __forceinline__ float fex2(float x) {
    float r; asm("ex2.approx.f32 %0, %1;" : "=f"(r) : "f"(x)); return r;
}
__device__ __forceinline__ float ftanh(float x) {
    float r; asm("tanh.approx.f32 %0, %1;" : "=f"(r) : "f"(x)); return r;
}
__device__ __forceinline__ u64 pk(float lo, float hi) {
    u64 d; asm("mov.b64 %0, {%1, %2};" : "=l"(d)
               : "r"(__float_as_uint(lo)), "r"(__float_as_uint(hi)));
    return d;
}
__device__ __forceinline__ void upk(float& lo, float& hi, u64 d) {
    unsigned a, b;
    asm("mov.b64 {%0, %1}, %2;" : "=r"(a), "=r"(b) : "l"(d));
    lo = __uint_as_float(a); hi = __uint_as_float(b);
}
__device__ __forceinline__ u64 fma2(u64 a, u64 b, u64 c) {
    u64 d; asm("fma.rn.f32x2 %0, %1, %2, %3;" : "=l"(d) : "l"(a), "l"(b), "l"(c));
    return d;
}
__device__ __forceinline__ u64 mul2(u64 a, u64 b) {
    u64 d; asm("mul.rn.f32x2 %0, %1, %2;" : "=l"(d) : "l"(a), "l"(b));
    return d;
}
__device__ __forceinline__ u64 add2(u64 a, u64 b) {
    u64 d; asm("add.rn.f32x2 %0, %1, %2;" : "=l"(d) : "l"(a), "l"(b));
    return d;
}
__device__ __forceinline__ void red4(float* addr, float a, float b, float c, float d) {
    asm volatile("red.global.v4.f32.add [%0], {%1, %2, %3, %4};"
                 :: "l"(addr), "f"(a), "f"(b), "f"(c), "f"(d) : "memory");
}

// ---------------------------------------------------------------------------
// L0: zero accumulators + w1s row sums.  grid = 320 x 256
// ---------------------------------------------------------------------------
__global__ __launch_bounds__(256) void init_kernel(const float* __restrict__ Wg)
{
    int bid = blockIdx.x;
    if (bid < 192) {
        int idx = bid * 256 + threadIdx.x;           // 0..49151
        float* arr = (idx < 16384) ? g_qp : (idx < 32768) ? g_kp : g_g2;
        *reinterpret_cast<float4*>(arr + (size_t)(idx & 16383) * 4) =
            make_float4(0.f, 0.f, 0.f, 0.f);
    } else {
        int gw   = (bid - 192) * 8 + (threadIdx.x >> 5);  // 0..1023
        int lane = threadIdx.x & 31;
        const float* row = Wg + (size_t)gw * (2 * DIM);
        float s = 0.f;
#pragma unroll
        for (int i = 0; i < 8; i++) {
            float4 v = *reinterpret_cast<const float4*>(&row[lane * 4 + i * 128]);
            s += v.x + v.y + v.z + v.w;
        }
#pragma unroll
        for (int o = 16; o; o >>= 1) s += __shfl_xor_sync(0xffffffffu, s, o);
        if (lane == 0) g_w1s[gw] = s;
    }
}

// ---------------------------------------------------------------------------
// Split-K GEMM, atomic accumulation into final buffer (no reduce pass).
// sel 0: qp = q @ Wq^T (+bq)   sel 1: kp = k @ Wk^T (+bk)   sel 2: g2 = kp @ W2^T (+bg)
// Tile 64(M) x 64(N); K-chunk = DIM / gridDim.y.
// ---------------------------------------------------------------------------
__global__ __launch_bounds__(256) void gemm_atom(
    int sel_base,
    const float* __restrict__ q, const float* __restrict__ k,
    const float* __restrict__ Wq, const float* __restrict__ Wk,
    const float* __restrict__ Wg,
    const float* __restrict__ bq, const float* __restrict__ bk,
    const float* __restrict__ bg)
{
    int sel = sel_base + blockIdx.z;
    const float* in;
    const float* W;
    const float* bias;
    float* dst;
    int ld, off;
    if (sel == 0)      { in = q;    W = Wq; ld = DIM;     off = 0;   dst = g_qp; bias = bq; }
    else if (sel == 1) { in = k;    W = Wk; ld = DIM;     off = 0;   dst = g_kp; bias = bk; }
    else               { in = g_kp; W = Wg; ld = 2 * DIM; off = DIM; dst = g_g2; bias = bg; }

    const int kchunk = DIM / gridDim.y;
    const int o0 = blockIdx.x * 64;
    const int k0 = blockIdx.y * kchunk;

    __shared__ __align__(16) float As[32][68];  // [k][m]
    __shared__ __align__(16) float Bs[32][68];  // [k][n]

    const int t  = threadIdx.x;
    const int tx = t & 15;   // n / 4
    const int ty = t >> 4;   // m / 4
    const int m0 = t >> 3;   // 0..31
    const int kq = t & 7;    // 0..7

    float acc[4][4];
#pragma unroll
    for (int i = 0; i < 4; i++)
#pragma unroll
        for (int j = 0; j < 4; j++) acc[i][j] = 0.f;

    // prefetch first chunk
    float4 va0, va1, vb0, vb1;
    {
        const float* ain = &in[k0 + kq * 4];
        const float* win = &W[(size_t)o0 * ld + off + k0 + kq * 4];
        va0 = *reinterpret_cast<const float4*>(&ain[(size_t)m0 * DIM]);
        va1 = *reinterpret_cast<const float4*>(&ain[(size_t)(m0 + 32) * DIM]);
        vb0 = *reinterpret_cast<const float4*>(&win[(size_t)m0 * ld]);
        vb1 = *reinterpret_cast<const float4*>(&win[(size_t)(m0 + 32) * ld]);
    }

    for (int kc = 0; kc < kchunk; kc += 32) {
        if (kc) __syncthreads();
        As[kq * 4 + 0][m0] = va0.x; As[kq * 4 + 1][m0] = va0.y;
        As[kq * 4 + 2][m0] = va0.z; As[kq * 4 + 3][m0] = va0.w;
        As[kq * 4 + 0][m0 + 32] = va1.x; As[kq * 4 + 1][m0 + 32] = va1.y;
        As[kq * 4 + 2][m0 + 32] = va1.z; As[kq * 4 + 3][m0 + 32] = va1.w;
        Bs[kq * 4 + 0][m0] = vb0.x; Bs[kq * 4 + 1][m0] = vb0.y;
        Bs[kq * 4 + 2][m0] = vb0.z; Bs[kq * 4 + 3][m0] = vb0.w;
        Bs[kq * 4 + 0][m0 + 32] = vb1.x; Bs[kq * 4 + 1][m0 + 32] = vb1.y;
        Bs[kq * 4 + 2][m0 + 32] = vb1.z; Bs[kq * 4 + 3][m0 + 32] = vb1.w;
        __syncthreads();
        if (kc + 32 < kchunk) {
            const float* ain = &in[k0 + kc + 32 + kq * 4];
            const float* win = &W[(size_t)o0 * ld + off + k0 + kc + 32 + kq * 4];
            va0 = *reinterpret_cast<const float4*>(&ain[(size_t)m0 * DIM]);
            va1 = *reinterpret_cast<const float4*>(&ain[(size_t)(m0 + 32) * DIM]);
            vb0 = *reinterpret_cast<const float4*>(&win[(size_t)m0 * ld]);
            vb1 = *reinterpret_cast<const float4*>(&win[(size_t)(m0 + 32) * ld]);
        }
#pragma unroll
        for (int kk = 0; kk < 32; kk++) {
            float4 a  = *reinterpret_cast<const float4*>(&As[kk][ty * 4]);
            float4 bv = *reinterpret_cast<const float4*>(&Bs[kk][tx * 4]);
            acc[0][0] = fmaf(a.x, bv.x, acc[0][0]);
            acc[0][1] = fmaf(a.x, bv.y, acc[0][1]);
            acc[0][2] = fmaf(a.x, bv.z, acc[0][2]);
            acc[0][3] = fmaf(a.x, bv.w, acc[0][3]);
            acc[1][0] = fmaf(a.y, bv.x, acc[1][0]);
            acc[1][1] = fmaf(a.y, bv.y, acc[1][1]);
            acc[1][2] = fmaf(a.y, bv.z, acc[1][2]);
            acc[1][3] = fmaf(a.y, bv.w, acc[1][3]);
            acc[2][0] = fmaf(a.z, bv.x, acc[2][0]);
            acc[2][1] = fmaf(a.z, bv.y, acc[2][1]);
            acc[2][2] = fmaf(a.z, bv.z, acc[2][2]);
            acc[2][3] = fmaf(a.z, bv.w, acc[2][3]);
            acc[3][0] = fmaf(a.w, bv.x, acc[3][0]);
            acc[3][1] = fmaf(a.w, bv.y, acc[3][1]);
            acc[3][2] = fmaf(a.w, bv.z, acc[3][2]);
            acc[3][3] = fmaf(a.w, bv.w, acc[3][3]);
        }
    }

    // split 0 carries the bias
    if (blockIdx.y == 0) {
        float b0 = bias[o0 + tx * 4 + 0];
        float b1 = bias[o0 + tx * 4 + 1];
        float b2 = bias[o0 + tx * 4 + 2];
        float b3 = bias[o0 + tx * 4 + 3];
#pragma unroll
        for (int i = 0; i < 4; i++) {
            acc[i][0] += b0; acc[i][1] += b1; acc[i][2] += b2; acc[i][3] += b3;
        }
    }

#pragma unroll
    for (int i = 0; i < 4; i++)
        red4(&dst[(ty * 4 + i) * DIM + o0 + tx * 4],
             acc[i][0], acc[i][1], acc[i][2], acc[i][3]);
}

// ---------------------------------------------------------------------------
// Fused scores*gate + softmax — WARP-AUTONOMOUS ROWS.
// Each warp owns a full row: lane covers j = lane*4 + c*128, c = 0..7.
// Pre-scaled coefficients (ap = kp*log2e, cw = w1s/2, cg = g2/2) live in smem
// (12 KB/block, filled once). Row sum is warp-local: 5 shfl, NO barriers in
// the main loop. All math packed f32x2; output via st.global.cs.v2.b64.
// Block = 256 thr (8 warps) x 4 rows/warp = 32 rows. grid = (64, 32).
// ---------------------------------------------------------------------------
__global__ __launch_bounds__(256) void fused_softmax(float* __restrict__ out)
{
    const int b   = blockIdx.x;
    const int i0  = blockIdx.y * ROWS;
    const int tid = threadIdx.x;

    __shared__ __align__(16) float s_ap[DIM];
    __shared__ __align__(16) float s_cw[DIM];
    __shared__ __align__(16) float s_cg[DIM];
    __shared__ float qs[ROWS];

    const float L2E = 1.4426950408889634f;
    // deg-5 minimax odd poly for sigma(u)-0.5, u in [-1,1] (err ~5e-6)
    const float A1 = 0.2499814f, A3 = -0.02068092f, A5 = 0.00176246f;
    const u64 A1p = pk(A1, A1), A3p = pk(A3, A3), A5p = pk(A5, A5);
    const u64 HALFp = pk(0.5f, 0.5f);

    // fill coefficient smem (each thread one float4 per array)
    {
        const int j0 = tid * 4;
        float4 kpv = *reinterpret_cast<const float4*>(&g_kp[b * DIM + j0]);
        float4 wv  = *reinterpret_cast<const float4*>(&g_w1s[j0]);
        float4 gv  = *reinterpret_cast<const float4*>(&g_g2[b * DIM + j0]);
        *reinterpret_cast<float4*>(&s_ap[j0]) =
            make_float4(kpv.x * L2E, kpv.y * L2E, kpv.z * L2E, kpv.w * L2E);
        *reinterpret_cast<float4*>(&s_cw[j0]) =
            make_float4(wv.x * 0.5f, wv.y * 0.5f, wv.z * 0.5f, wv.w * 0.5f);
        *reinterpret_cast<float4*>(&s_cg[j0]) =
            make_float4(gv.x * 0.5f, gv.y * 0.5f, gv.z * 0.5f, gv.w * 0.5f);
        if (tid < ROWS) qs[tid] = g_qp[b * DIM + i0 + tid];
    }
    __syncthreads();

    const int w = tid >> 5, lane = tid & 31;
    const int jbase = lane * 4;

#pragma unroll 1
    for (int rr = 0; rr < 4; rr++) {
        const int r = w + rr * 8;
        const float qi = qs[r];
        const u64 qip = pk(qi, qi);

        u64 ep[16];
        u64 sum2 = 0;  // packed 0.0,0.0
#pragma unroll
        for (int c = 0; c < 8; c++) {
            const int j = jbase + c * 128;
            float4 av = *reinterpret_cast<const float4*>(&s_ap[j]);
            float4 wv = *reinterpret_cast<const float4*>(&s_cw[j]);
            float4 gv = *reinterpret_cast<const float4*>(&s_cg[j]);
#pragma unroll
            for (int p = 0; p < 2; p++) {
                const u64 cwp = p ? pk(wv.z, wv.w) : pk(wv.x, wv.y);
                const u64 cgp = p ? pk(gv.z, gv.w) : pk(gv.x, gv.y);
                const u64 app = p ? pk(av.z, av.w) : pk(av.x, av.y);
                u64 argp = fma2(qip, cwp, cgp);              // gate_pre / 2
                float a0, a1; upk(a0, a1, argp);
                float th0 = ftanh(a0), th1 = ftanh(a1);
                u64 s1p = fma2(pk(th0, th1), HALFp, HALFp);  // inner sigmoid
                u64 z2  = mul2(s1p, s1p);
                u64 pp  = fma2(z2, A5p, A3p);                // minimax deg-5
                pp      = fma2(z2, pp, A1p);
                u64 gatep = fma2(s1p, pp, HALFp);            // outer sigmoid
                u64 eargp = mul2(mul2(qip, app), gatep);     // L2E*score*gate
                float e0a, e1a; upk(e0a, e1a, eargp);
                u64 ev = pk(fex2(e0a), fex2(e1a));
                ep[c * 2 + p] = ev;
                sum2 = add2(sum2, ev);
            }
        }
        float slo, shi; upk(slo, shi, sum2);
        float loc = slo + shi;
#pragma unroll
        for (int o = 16; o; o >>= 1) loc += __shfl_xor_sync(0xffffffffu, loc, o);
        const float inv = frcp(loc);
        const u64 invp = pk(inv, inv);

        float* orow = out + ((size_t)(b * DIM + i0 + r)) * DIM + jbase;
#pragma unroll
        for (int c = 0; c < 8; c++) {
            u64 o0v = mul2(ep[c * 2 + 0], invp);
            u64 o1v = mul2(ep[c * 2 + 1], invp);
            asm volatile("st.global.cs.v2.b64 [%0], {%1, %2};"
                         :: "l"(orow + c * 128), "l"(o0v), "l"(o1v) : "memory");
        }
    }
}

extern "C" void kernel_launch(void* const* d_in, const int* in_sizes, int n_in,
                              void* d_out, int out_size)
{
    const float* q  = (const float*)d_in[0];
    const float* k  = (const float*)d_in[1];
    // d_in[2] = v : unused by the reference
    const float* Wq = (const float*)d_in[3];
    const float* bq = (const float*)d_in[4];
    const float* Wk = (const float*)d_in[5];
    const float* bk = (const float*)d_in[6];
    const float* Wg = (const float*)d_in[7];
    const float* bg = (const float*)d_in[8];
    float* out = (float*)d_out;

    // L0: zero accumulators + w1s
    init_kernel<<<320, 256>>>(Wg);
    // L1: qp & kp (atomic split-K, KSPLIT=16 -> 512 blocks)
    gemm_atom<<<dim3(16, 16, 2), 256>>>(0, q, k, Wq, Wk, Wg, bq, bk, bg);
    // L2: g2 = kp @ W2^T (atomic split-K, KSPLIT=32 -> 512 blocks)
    gemm_atom<<<dim3(16, 32, 1), 256>>>(2, q, k, Wq, Wk, Wg, bq, bk, bg);
    // L3: fused scores/gate/softmax — one pass over the 256 MB output
    fused_softmax<<<dim3(BATCH, DIM / ROWS), 256>>>(out);
}